// round 10
// baseline (speedup 1.0000x reference)
#include <cuda_runtime.h>
#include <cstdint>

#define H 256
#define W 256
#define K 512
#define Z_THRESHOLD 3.0f
#define EPS 1e-08f

// sqrt(0.5 * log2(e)): folded into inverse scales so gauss = exp2(-(dx'^2+dy'^2))
#define SCALE_C 0.84932180028801904f

#define TPB   128            // threads per block (half an image row)
#define GPT   4              // gaussians per thread (K / TPB)
#define GRID  (H * 2)        // 512 blocks, ~4 resident per SM

// Cull threshold: max window alpha < 2^-20 ~ 1e-6 -> skipped gaussian perturbs
// a pixel by < ~6e-5 absolute; rel tolerance is 1e-3.
#define CULL_LOG2 -20.0f

// ---------------------------------------------------------------------------
// Fused kernel, half-row blocks. Block b covers row b>>1, columns
// [(b&1)*128, (b&1)*128+128). Because the row is fixed, dx'^2 folds into a
// per-gaussian constant; the column window additionally bounds dy'^2 for a
// tighter cull.
//   1) prep: each thread computes 4 gaussians' eff_w, folded exponent peak
//      top = log2(eff_w) - dx'^2, and the window dy'^2 lower bound,
//   2) cull-compact: survivors' keys AND params are written directly at their
//      compacted slots (no unsorted staging array, no gather),
//   3) rank sort over the ~6 survivors (unique keys embed original idx ->
//      exact stable argsort(-eff_w) order restricted to survivors),
//   4) render: 1 px/thread, 9-instr inner loop.
// 3 barriers, every loop tiny, ~4 blocks/SM overlap the latency.
// ---------------------------------------------------------------------------
__global__ void __launch_bounds__(TPB, 8)
fused_kernel(const float* __restrict__ positions,   // [K,3]
             const float* __restrict__ scales,      // [K,3]
             const float* __restrict__ opacity,     // [K]
             const float* __restrict__ intensity,   // [K]
             const float* __restrict__ z_target,    // [1]
             float* __restrict__ out)               // [H*W]
{
    __shared__ unsigned long long sk[K];  // compacted survivor keys
    __shared__ float4 cpk[K];             // compact-order survivor params
    __shared__ float4 csp[K];             // rank-ordered survivor params
    __shared__ int    sCnt;

    const int tid  = threadIdx.x;
    const int lane = tid & 31;
    const float fy = (float)(blockIdx.x >> 1);        // image row
    const float c0 = (float)((blockIdx.x & 1) << 7);  // window first column
    const float c1 = c0 + 127.0f;                     // window last column

    if (tid == 0) sCnt = 0;

    // ---- prep + cull test for 4 gaussians per thread ----
    const float zt = z_target[0];
    bool   kp[GPT];
    unsigned long long kk[GPT];
    float4 pr[GPT];

    #pragma unroll
    for (int s = 0; s < GPT; ++s) {
        const int g = tid + s * TPB;                  // warp-coalesced
        const float px  = positions[g * 3 + 0];
        const float py  = positions[g * 3 + 1];
        const float pz  = positions[g * 3 + 2];
        const float isx = __fdividef(SCALE_C, scales[g * 3 + 0] + EPS);
        const float isy = __fdividef(SCALE_C, scales[g * 3 + 1] + EPS);
        const float sz  = scales[g * 3 + 2];

        const float zd = __fdividef(zt - pz, sz + EPS);
        float w = 0.0f;
        if (fabsf(zd) < Z_THRESHOLD) {
            w = opacity[g] * __expf(-0.5f * zd * zd);
        }

        const float dxp = (fy - px) * isx;            // row-constant dx'
        const float top = __log2f(w) - dxp * dxp;     // -inf when w == 0

        // dy'^2 lower bound over the column window [c0, c1]
        const float dy0 = (c0 - py) * isy;
        const float dy1 = (c1 - py) * isy;
        const float dymin2 = (dy0 * dy1 > 0.0f) ? fminf(dy0 * dy0, dy1 * dy1)
                                                : 0.0f;

        kp[s] = (top - dymin2 > CULL_LOG2);           // w=0 -> top=-inf -> out

        // Ascending uint64 order == descending eff_w, ascending idx on ties
        // (stable argsort(-eff_w); keys unique via embedded idx).
        const unsigned int wb = __float_as_uint(w);   // w >= 0: bits monotone
        kk[s] = ((unsigned long long)(~wb) << 32) | (unsigned int)g;

        pr[s] = make_float4(isy, -py * isy, top, intensity[g]);
    }
    __syncthreads();   // sCnt = 0 visible before atomicAdd

    // ---- cull-compact: keys + params straight to compacted slots ----
    unsigned int m[GPT];
    int cnt = 0;
    #pragma unroll
    for (int s = 0; s < GPT; ++s) {
        m[s] = __ballot_sync(0xFFFFFFFFu, kp[s]);
        cnt += __popc(m[s]);
    }
    int base = 0;
    if (lane == 0 && cnt) base = atomicAdd(&sCnt, cnt);
    base = __shfl_sync(0xFFFFFFFFu, base, 0);
    const unsigned int ltmask = (1u << lane) - 1u;
    #pragma unroll
    for (int s = 0; s < GPT; ++s) {
        if (kp[s]) {
            int pos = base + __popc(m[s] & ltmask);
            sk[pos]  = kk[s];
            cpk[pos] = pr[s];
        }
        base += __popc(m[s]);
    }
    __syncthreads();

    const int Mc = sCnt;

    // ---- rank sort over the Mc survivors ----
    if (tid < Mc) {
        const unsigned long long mykey = sk[tid];
        int rank = 0;
        for (int j = 0; j < Mc; ++j) {
            rank += (sk[j] < mykey);   // broadcast LDS, unique keys
        }
        csp[rank] = cpk[tid];
    }
    __syncthreads();

    // ---- render: one pixel per thread ----
    const float fx = c0 + (float)tid;     // column (positions[:,1])

    float T = 1.0f;
    float A = 0.0f;

    #pragma unroll 4
    for (int j = 0; j < Mc; ++j) {
        const float4 P = csp[j];

        float dy  = fmaf(fx, P.x, P.y);        // (fx - py) * isy'
        float arg = fmaf(dy, -dy, P.z);        // top - dy'^2

        float ga;                              // == gauss * eff_w
        asm("ex2.approx.ftz.f32 %0, %1;" : "=f"(ga) : "f"(arg));

        float a  = fminf(ga, 0.99f);
        float ta = T * a;
        A = fmaf(ta, P.w, A);
        T -= ta;
    }

    out[(blockIdx.x >> 1) * W + ((blockIdx.x & 1) << 7) + tid] = A;
}

extern "C" void kernel_launch(void* const* d_in, const int* in_sizes, int n_in,
                              void* d_out, int out_size)
{
    const float* positions = (const float*)d_in[0];
    const float* scales    = (const float*)d_in[1];
    const float* opacity   = (const float*)d_in[2];
    const float* intensity = (const float*)d_in[3];
    const float* z_target  = (const float*)d_in[4];
    float* out = (float*)d_out;

    fused_kernel<<<GRID, TPB>>>(positions, scales, opacity, intensity,
                                z_target, out);
}